// round 8
// baseline (speedup 1.0000x reference)
#include <cuda_runtime.h>
#include <cuda_fp16.h>
#include <stdint.h>

#define R_NODES   256
#define N_STEPS   512
#define M_SAMP    512
#define OUT_DIM   10
#define LUT_WORDS 8192            // 2^18 bits / 32
#define NPC       4               // samples per CTA (2 pipelined groups of 2)
#define N_CTA     (M_SAMP / NPC)  // 128 CTAs -> ~1 per SM
#define RB_STRIDE 264             // halfs per row: banks (g*132+tg)%32 distinct
#define MAGIC_F   8388608.0f      // 2^23: accumulator mantissa low 23 bits == integer sum

// Scratch: __device__ globals (no allocation allowed)
__device__ unsigned g_lut_bits[R_NODES * LUT_WORDS]; // 8 MB bit-packed LUT
__device__ unsigned g_x_bits[M_SAMP * N_STEPS];      // 1 MB bit-packed inputs

// ---------------------------------------------------------------------------
// Pack LUT (flat): word w, bit b = lut[w*32 + b]. MLP=32 load stage then ballots.
// ---------------------------------------------------------------------------
__global__ void pack_lut_kernel(const int* __restrict__ lut) {
    const int warp_g = (blockIdx.x * blockDim.x + threadIdx.x) >> 5;
    const int lane   = threadIdx.x & 31;
    const int w0     = warp_g * 32;
    const unsigned* src = (const unsigned*)lut;
    unsigned v[32];
    #pragma unroll
    for (int i = 0; i < 32; i++)
        v[i] = src[(size_t)(w0 + i) * 32 + lane];
    unsigned myw = 0;
    #pragma unroll
    for (int i = 0; i < 32; i++) {
        unsigned b = __ballot_sync(0xFFFFFFFFu, v[i] & 1u);
        if (i == lane) myw = b;
    }
    g_lut_bits[w0 + lane] = myw;
}

// ---------------------------------------------------------------------------
// Pack x: int32[512][512][4][8] (0/1) -> g_x_bits[m*512 + t], bit i = feature i
// ---------------------------------------------------------------------------
__global__ void pack_x_kernel(const int* __restrict__ x) {
    int w = blockIdx.x * blockDim.x + threadIdx.x;
    if (w >= M_SAMP * N_STEPS) return;
    const uint4* p = (const uint4*)(x + (size_t)w * 32);
    unsigned word = 0;
    #pragma unroll
    for (int j = 0; j < 8; j++) {
        uint4 v = p[j];
        word |= (v.x & 1u) << (4 * j + 0);
        word |= (v.y & 1u) << (4 * j + 1);
        word |= (v.z & 1u) << (4 * j + 2);
        word |= (v.w & 1u) << (4 * j + 3);
    }
    g_x_bits[w] = word;
}

// ---------------------------------------------------------------------------
// m16n8k16 fp16 MMA, fp32 accumulate (exact for our integer ranges)
// ---------------------------------------------------------------------------
__device__ __forceinline__ void mma16816(float* d, const unsigned* a, unsigned b0, unsigned b1) {
    asm volatile(
        "mma.sync.aligned.m16n8k16.row.col.f32.f16.f16.f32 "
        "{%0,%1,%2,%3}, {%4,%5,%6,%7}, {%8,%9}, {%0,%1,%2,%3};\n"
        : "+f"(d[0]), "+f"(d[1]), "+f"(d[2]), "+f"(d[3])
        : "r"(a[0]), "r"(a[1]), "r"(a[2]), "r"(a[3]), "r"(b0), "r"(b1));
}

// ---------------------------------------------------------------------------
// Reservoir kernel: 128 CTAs x 256 threads; CTA b owns samples [4b, 4b+4) as
// two pipelined groups of 2 (tiles tA = samples 0-1, tB = samples 2-3).
// Warp w holds Wp rows for nodes [32w,32w+32) in 128 registers.
// Per half-step: issue group-i's scattered LUT loads, run group-j's MMA chain
// while they fly (LSU/tensor overlap), then consume + store + sync.
// ---------------------------------------------------------------------------
__global__ void __launch_bounds__(256, 1)
reservoir_kernel(const int* __restrict__ input_nodes,
                 const int* __restrict__ Wres,
                 const int* __restrict__ primes,
                 const int* __restrict__ init_res,
                 const float* __restrict__ readout_W,
                 const float* __restrict__ readout_b,
                 float* __restrict__ out)
{
    __shared__ __half tA[8][RB_STRIDE];          // group 0 state (rows 0-1; 2-7 zero)
    __shared__ __half tB[8][RB_STRIDE];          // group 1 state (rows 0-1; 2-7 zero)
    __shared__ short s_inp[R_NODES];
    __shared__ int s_innodes[32];
    __shared__ unsigned short s_ph[R_NODES];
    __shared__ float s_W[OUT_DIM * R_NODES];

    const int tid  = threadIdx.x;
    const int wid  = tid >> 5;
    const int lane = tid & 31;
    const int g    = lane >> 2;                  // MMA row-in-tile
    const int tg   = lane & 3;
    const int mbase = blockIdx.x * NPC;
    const __half ONE  = __ushort_as_half(0x3C00);
    const __half ZERO = __ushort_as_half(0x0000);

    // ---- tables ----
    s_inp[tid] = -1;
    s_ph[tid]  = __half_as_ushort(__int2half_rn(primes[tid]));
    for (int i = tid; i < OUT_DIM * R_NODES; i += 256) s_W[i] = readout_W[i];
    __syncthreads();
    if (tid < 32) {
        int nn = input_nodes[tid];
        s_innodes[tid] = nn;
        s_inp[nn] = (short)tid;
    }

    // ---- A fragments (Wp = Wres ? prime : 0), register-resident ----
    unsigned A[16][2][4];
    const int node_base = wid * 32;
    #pragma unroll
    for (int kt = 0; kt < 16; kt++) {
        #pragma unroll
        for (int mt = 0; mt < 2; mt++) {
            #pragma unroll
            for (int r = 0; r < 4; r++) {
                int row = node_base + mt * 16 + g + ((r & 1) ? 8 : 0);
                int k0  = kt * 16 + tg * 2 + ((r & 2) ? 8 : 0);
                unsigned h0 = Wres[row * 256 + k0]     ? (unsigned)s_ph[k0]     : 0u;
                unsigned h1 = Wres[row * 256 + k0 + 1] ? (unsigned)s_ph[k0 + 1] : 0u;
                A[kt][mt][r] = h0 | (h1 << 16);
            }
        }
    }

    // ---- init tiles: rows 0-1 = init_res, rows 2-7 = zero; then x_0 ----
    {
        __half v = init_res[tid] ? ONE : ZERO;
        tA[0][tid] = v; tA[1][tid] = v;
        tB[0][tid] = v; tB[1][tid] = v;
        #pragma unroll
        for (int s = 2; s < 8; s++) { tA[s][tid] = ZERO; tB[s][tid] = ZERO; }
    }
    __syncthreads();
    if (tid < NPC * 32) {
        int s = tid >> 5, i = tid & 31;          // local sample s (0-3), feature i
        unsigned xb = (g_x_bits[(size_t)(mbase + s) * N_STEPS + 0] >> i) & 1u;
        __half v = xb ? ONE : ZERO;
        if (s < 2) tA[s][s_innodes[i]] = v; else tB[s - 2][s_innodes[i]] = v;
    }
    __syncthreads();

    // ---- per-lane gather constants (valid work on tg==0 lanes only) ----
    // j = mt*2 + h : node = node_base + mt*16 + g + h*8 ; value e -> j=(e>>1)+mt*2, sample=e&1
    const unsigned* lp[4];
    int nds[4];
    bool is_inp[4];
    #pragma unroll
    for (int j = 0; j < 4; j++) {
        int n = node_base + (j >> 1) * 16 + g + (j & 1) * 8;
        nds[j] = n;
        lp[j]  = g_lut_bits + (size_t)n * LUT_WORDS;
        is_inp[j] = (s_inp[n] >= 0);
    }
    const bool gatherer = (tg == 0);
    // x-overwrite role: threads 0..127 -> local sample tid>>5, feature tid&31
    const int xs = tid >> 5, xi = tid & 31;
    const int xnode = (tid < NPC * 32) ? s_innodes[xi] : 0;
    const unsigned* xrow = g_x_bits + (size_t)(mbase + (xs & (NPC - 1))) * N_STEPS;

    // MMA over a tile -> 8 packed integer indices (valid on tg==0)
    auto run_mma = [&](const __half (*tile)[RB_STRIDE], unsigned* u) {
        float d[2][4][4];
        #pragma unroll
        for (int mt = 0; mt < 2; mt++)
            #pragma unroll
            for (int c = 0; c < 4; c++)
                #pragma unroll
                for (int e = 0; e < 4; e++)
                    d[mt][c][e] = (c == 0) ? MAGIC_F : 0.0f;
        #pragma unroll
        for (int kt = 0; kt < 16; kt++) {
            unsigned b0 = *(const unsigned*)&tile[g][kt * 16 + tg * 2];
            unsigned b1 = *(const unsigned*)&tile[g][kt * 16 + tg * 2 + 8];
            mma16816(d[0][kt & 3], A[kt][0], b0, b1);
            mma16816(d[1][kt & 3], A[kt][1], b0, b1);
        }
        #pragma unroll
        for (int mt = 0; mt < 2; mt++)
            #pragma unroll
            for (int e = 0; e < 4; e++) {
                float tot = (d[mt][0][e] + d[mt][1][e]) + (d[mt][2][e] + d[mt][3][e]);
                u[mt * 4 + e] = __float_as_uint(tot) & 0x7FFFFFu;
            }
    };
    // issue the (up to 8) scattered LUT word loads for a group
    auto issue_loads = [&](const unsigned* u, unsigned* w, bool last) {
        #pragma unroll
        for (int k = 0; k < 8; k++) {
            int j = (k >> 2) * 2 + ((k & 3) >> 1);
            if (last || !is_inp[j]) w[k] = lp[j][u[k] >> 5];
        }
    };
    // consume loads -> write new state into tile rows 0/1
    auto consume = [&](__half (*tile)[RB_STRIDE], const unsigned* u, const unsigned* w, bool last) {
        #pragma unroll
        for (int k = 0; k < 8; k++) {
            int j = (k >> 2) * 2 + ((k & 3) >> 1);
            if (last || !is_inp[j])
                tile[k & 1][nds[j]] = ((w[k] >> (u[k] & 31)) & 1u) ? ONE : ZERO;
        }
    };

    // ---- pipelined 512 steps: group0 (tA) leads, group1 (tB) follows ----
    unsigned u0[8], u1[8];
    run_mma(tA, u0);                             // prologue: idx for group0, t=0

    for (int t = 0; t < N_STEPS; t++) {
        const bool last = (t == N_STEPS - 1);

        // prefetch x_{t+1} word (both groups' writers are threads 0..127)
        unsigned xw = 0;
        if (!last && tid < NPC * 32) xw = xrow[t + 1];

        unsigned w0[8], w1[8];
        if (gatherer) issue_loads(u0, w0, last); // group0 loads fly...
        run_mma(tB, u1);                         // ...under group1 tensor work
        if (gatherer) consume(tA, u0, w0, last);
        if (!last && xs < 2)                     // x_{t+1} for group0
            tA[xs][xnode] = ((xw >> xi) & 1u) ? ONE : ZERO;
        __syncthreads();                         // tA state(t+1) complete

        if (gatherer) issue_loads(u1, w1, last); // group1 loads fly...
        if (!last) run_mma(tA, u0);              // ...under group0 tensor work (t+1)
        if (gatherer) consume(tB, u1, w1, last);
        if (!last && tid < NPC * 32 && xs >= 2)  // x_{t+1} for group1
            tB[xs - 2][xnode] = ((xw >> xi) & 1u) ? ONE : ZERO;
        __syncthreads();                         // tB state(t+1) complete
    }

    // ---- readout: warps 0-3, warp w -> local sample w ----
    if (wid < NPC) {
        const __half* st = (wid < 2) ? &tA[wid][0] : &tB[wid - 2][0];
        float acc[OUT_DIM];
        #pragma unroll
        for (int o = 0; o < OUT_DIM; o++) acc[o] = 0.0f;
        #pragma unroll
        for (int kk = 0; kk < 8; kk++) {
            int k = lane + kk * 32;
            float rv = __half2float(st[k]);
            #pragma unroll
            for (int o = 0; o < OUT_DIM; o++)
                acc[o] += rv * s_W[o * R_NODES + k];
        }
        #pragma unroll
        for (int o = 0; o < OUT_DIM; o++) {
            #pragma unroll
            for (int off = 16; off; off >>= 1)
                acc[o] += __shfl_xor_sync(0xFFFFFFFFu, acc[o], off);
        }
        if (lane == 0) {
            #pragma unroll
            for (int o = 0; o < OUT_DIM; o++)
                out[(mbase + wid) * OUT_DIM + o] = acc[o] + readout_b[o];
        }
    }
}

// ---------------------------------------------------------------------------
// kernel_launch. Inputs: x, input_nodes, lut, W_res, primes, init_res,
// readout_W, readout_b (bool arrays delivered as int32).
// ---------------------------------------------------------------------------
extern "C" void kernel_launch(void* const* d_in, const int* in_sizes, int n_in,
                              void* d_out, int out_size) {
    const int*   x        = (const int*)d_in[0];
    const int*   in_nodes = (const int*)d_in[1];
    const int*   lut      = (const int*)d_in[2];
    const int*   Wres     = (const int*)d_in[3];
    const int*   primes   = (const int*)d_in[4];
    const int*   init_res = (const int*)d_in[5];
    const float* rW       = (const float*)d_in[6];
    const float* rb       = (const float*)d_in[7];
    float*       out      = (float*)d_out;

    pack_lut_kernel<<<(R_NODES * LUT_WORDS) / (32 * 8), 256>>>(lut);
    pack_x_kernel<<<(M_SAMP * N_STEPS) / 256, 256>>>(x);
    reservoir_kernel<<<N_CTA, 256>>>(in_nodes, Wres, primes, init_res, rW, rb, out);
}